// round 12
// baseline (speedup 1.0000x reference)
#include <cuda_runtime.h>

// ---------------------------------------------------------------------------
// PureGNN rank collapse, u-scaled form, multi-launch + PDL:
//   u_k = dinv .* z_k ; edge: acc[d] += u_k[s] ; node: z=dinv*(acc+u), u=dinv*z
// Basis after 3 layers: [P^3 x, P^3 1, P^2 1, P 1, 1]; pooled S -> tiny readout.
// Self-restoring invariants (no init kernel): g_deg==0 restored by k_prep,
// g_S==0 restored by k_readout; loader zero-init provides the first epoch.
// RULES: __device__ globals only referenced in device code (ATS trap).
//        PDL pre-sync code reads ONLY pure inputs or K-2-or-older data.
//        Edge kernels: 2 edges/thread, low regs -> max occupancy (R10 lesson).
// ---------------------------------------------------------------------------

#define NN 50000
#define NE 1600000
#define NG 32
#define ED 128

__device__ float  g_deg [NN];     // invariant: 0 at kernel_launch entry
__device__ float  g_dinv[NN];
__device__ float2 g_u   [NN];     // current u_k
__device__ float2 g_acc [NN];     // edge accumulator
__device__ float  g_k1y [NN];     // z1.y
__device__ float  g_k2y [NN];     // z2.y
__device__ float  g_S   [NG * 5]; // invariant: 0 at kernel_launch entry

// ---------------------------------------------------------------------------
// degree count: 8 edges/thread, indices pre-loaded (pure input); deg starts 0.
__global__ void k_count(const int* __restrict__ dst) {
    int e = (blockIdx.x * blockDim.x + threadIdx.x) * 8;
    int4 a, b;
    bool full = (e + 7 < NE);
    if (full) {
        a = *(const int4*)(dst + e);
        b = *(const int4*)(dst + e + 4);
    }
    cudaGridDependencySynchronize();   // previous replay's readout done
    if (full) {
        atomicAdd(&g_deg[a.x], 1.0f);
        atomicAdd(&g_deg[a.y], 1.0f);
        atomicAdd(&g_deg[a.z], 1.0f);
        atomicAdd(&g_deg[a.w], 1.0f);
        atomicAdd(&g_deg[b.x], 1.0f);
        atomicAdd(&g_deg[b.y], 1.0f);
        atomicAdd(&g_deg[b.z], 1.0f);
        atomicAdd(&g_deg[b.w], 1.0f);
    } else {
        for (; e < NE; e++) atomicAdd(&g_deg[dst[e]], 1.0f);
    }
    cudaTriggerProgrammaticLaunchCompletion();
}

// dinv = rsqrt(deg+1)  (+1 = self-loop); restore deg=0; u0; acc=0
__global__ void k_prep(const float* __restrict__ x) {
    int i = blockIdx.x * blockDim.x + threadIdx.x;
    float xi = 0.0f;
    if (i < NN) xi = x[i];
    cudaGridDependencySynchronize();               // wait for k_count
    if (i >= NN) return;
    float di = rsqrtf(g_deg[i] + 1.0f);
    g_deg[i] = 0.0f;                               // restore invariant
    g_dinv[i] = di;
    g_u[i]   = make_float2(di * xi, di);
    g_acc[i] = make_float2(0.0f, 0.0f);
}

// edge pass: acc[d] += u[s], 2 edges/thread (low regs, high occupancy)
__global__ void k_edge(const int* __restrict__ src, const int* __restrict__ dst) {
    int e = (blockIdx.x * blockDim.x + threadIdx.x) * 2;
    int2 s2, d2;
    bool full = (e + 1 < NE);
    if (full) {                                    // pure input: safe pre-sync
        s2 = *(const int2*)(src + e);
        d2 = *(const int2*)(dst + e);
    }
    cudaGridDependencySynchronize();               // wait for u from prior kernel
    if (full) {
        float2 v0 = __ldg(&g_u[s2.x]);
        float2 v1 = __ldg(&g_u[s2.y]);
        atomicAdd(&g_acc[d2.x], v0);
        atomicAdd(&g_acc[d2.y], v1);
    } else if (e < NE) {
        atomicAdd(&g_acc[dst[e]], __ldg(&g_u[src[e]]));
    }
    cudaTriggerProgrammaticLaunchCompletion();
}

// node pass K (1 or 2): z = dinv*(acc+u); stash z.y; u = dinv*z; acc = 0
// dinv/u are K-2-or-older -> safe pre-sync; acc needs the sync.
template <int K>
__global__ void k_node() {
    int i = blockIdx.x * blockDim.x + threadIdx.x;
    float di = 0.0f; float2 u = make_float2(0.0f, 0.0f);
    if (i < NN) { di = g_dinv[i]; u = g_u[i]; }
    cudaGridDependencySynchronize();               // wait for acc from edge pass
    if (i >= NN) return;
    float2 a = g_acc[i];
    float zx = di * (a.x + u.x);
    float zy = di * (a.y + u.y);
    if (K == 1) g_k1y[i] = zy;
    else        g_k2y[i] = zy;
    g_u[i]   = make_float2(di * zx, di * zy);
    g_acc[i] = make_float2(0.0f, 0.0f);
}

// node3 + per-graph pooling (batch sorted -> warp-uniform fast path).
__global__ void k_node3_pool(const int* __restrict__ batch) {
    __shared__ float sh[NG * 5];
    int i = blockIdx.x * blockDim.x + threadIdx.x;
    int lane = threadIdx.x & 31;
    bool act = (i < NN);
    int g = 0;
    if (act) g = batch[i];                         // pure input: safe pre-sync
    for (int t = threadIdx.x; t < NG * 5; t += blockDim.x) sh[t] = 0.0f;
    __syncthreads();

    cudaGridDependencySynchronize();               // wait for acc3

    float z3x = 0.0f, z3y = 0.0f, k2 = 0.0f, k1 = 0.0f;
    if (act) {
        float di = g_dinv[i];
        float2 a = g_acc[i];
        float2 u = g_u[i];
        z3x = di * (a.x + u.x);
        z3y = di * (a.y + u.y);
        k2  = g_k2y[i];
        k1  = g_k1y[i];
    }
    unsigned m = __ballot_sync(0xffffffffu, act);
    int g0 = __shfl_sync(0xffffffffu, g, 0);
    bool uni = (m == 0xffffffffu) && __all_sync(0xffffffffu, g == g0);
    if (uni) {
        #pragma unroll
        for (int o = 16; o > 0; o >>= 1) {
            z3x += __shfl_down_sync(0xffffffffu, z3x, o);
            z3y += __shfl_down_sync(0xffffffffu, z3y, o);
            k2  += __shfl_down_sync(0xffffffffu, k2,  o);
            k1  += __shfl_down_sync(0xffffffffu, k1,  o);
        }
        if (lane == 0) {
            atomicAdd(&sh[g0 * 5 + 0], z3x);
            atomicAdd(&sh[g0 * 5 + 1], z3y);
            atomicAdd(&sh[g0 * 5 + 2], k2);
            atomicAdd(&sh[g0 * 5 + 3], k1);
            atomicAdd(&sh[g0 * 5 + 4], 32.0f);
        }
    } else if (act) {
        atomicAdd(&sh[g * 5 + 0], z3x);
        atomicAdd(&sh[g * 5 + 1], z3y);
        atomicAdd(&sh[g * 5 + 2], k2);
        atomicAdd(&sh[g * 5 + 3], k1);
        atomicAdd(&sh[g * 5 + 4], 1.0f);
    }
    __syncthreads();
    for (int t = threadIdx.x; t < NG * 5; t += blockDim.x)
        if (sh[t] != 0.0f) atomicAdd(&g_S[t], sh[t]);
    cudaTriggerProgrammaticLaunchCompletion();
}

// ---------------------------------------------------------------------------
// Readout (PDL): weight chain pre-sync (overlaps the pool); g_S read post-sync
// and zeroed to restore the replay invariant.
// ---------------------------------------------------------------------------
__global__ void k_readout(const float* __restrict__ lin_w, const float* __restrict__ lin_b,
                          const float* __restrict__ gcn_w, const float* __restrict__ gcn_b,
                          const float* __restrict__ r1_w,  const float* __restrict__ r1_b,
                          const float* __restrict__ r2_w,  const float* __restrict__ r2_b,
                          float* __restrict__ out) {
    __shared__ float vin[5][ED];
    __shared__ float vout[5][ED];
    __shared__ float pooled[NG][ED];
    __shared__ float hr[NG][ED];
    __shared__ float sS[NG * 5];

    int tid = threadIdx.x;
    int j   = tid & 127;
    int grp = tid >> 7;      // 0..3

    if (grp == 0) { vin[0][j] = lin_w[j]; vin[1][j] = lin_b[j]; }  // pure inputs
    __syncthreads();

    int nrows = 2;
    for (int l = 0; l < 3; l++) {
        const float* W = gcn_w + l * ED * ED;
        if (grp < nrows) {
            float a0 = 0.0f, a1 = 0.0f;
            #pragma unroll 4
            for (int i = 0; i < ED; i += 2) {
                a0 = fmaf(vin[grp][i],     W[i * ED + j],       a0);
                a1 = fmaf(vin[grp][i + 1], W[(i + 1) * ED + j], a1);
            }
            vout[grp][j] = a0 + a1;
        }
        if (grp == 0) vout[nrows][j] = gcn_b[l * ED + j];
        nrows++;
        __syncthreads();
        for (int r = grp; r < nrows; r += 4) vin[r][j] = vout[r][j];
        __syncthreads();
    }

    cudaGridDependencySynchronize();          // g_S ready
    for (int t = tid; t < NG * 5; t += 512) { sS[t] = g_S[t]; g_S[t] = 0.0f; }
    __syncthreads();

    for (int g = grp * 8; g < grp * 8 + 8; g++) {
        float p = 0.0f;
        #pragma unroll
        for (int r = 0; r < 5; r++) p = fmaf(sS[g * 5 + r], vin[r][j], p);
        pooled[g][j] = p;
    }
    __syncthreads();

    float bj = r1_b[j];
    for (int g = grp * 8; g < grp * 8 + 8; g++) {
        float a0 = bj, a1 = 0.0f, a2 = 0.0f, a3 = 0.0f;
        #pragma unroll 2
        for (int i = 0; i < ED; i += 4) {
            a0 = fmaf(pooled[g][i],     r1_w[i * ED + j],       a0);
            a1 = fmaf(pooled[g][i + 1], r1_w[(i + 1) * ED + j], a1);
            a2 = fmaf(pooled[g][i + 2], r1_w[(i + 2) * ED + j], a2);
            a3 = fmaf(pooled[g][i + 3], r1_w[(i + 3) * ED + j], a3);
        }
        hr[g][j] = tanhf((a0 + a1) + (a2 + a3));
    }
    __syncthreads();

    int warp = tid >> 5;
    int lane = tid & 31;
    for (int g = warp; g < NG; g += 16) {
        float s = hr[g][lane]      * r2_w[lane]
                + hr[g][lane + 32] * r2_w[lane + 32]
                + hr[g][lane + 64] * r2_w[lane + 64]
                + hr[g][lane + 96] * r2_w[lane + 96];
        #pragma unroll
        for (int o = 16; o > 0; o >>= 1) s += __shfl_down_sync(0xffffffffu, s, o);
        if (lane == 0) out[g] = s + r2_b[0];
    }
}

// ---------------------------------------------------------------------------
template <typename KernT, typename... Args>
static inline void launch_pdl(KernT kern, int grid, int block, Args... args) {
    cudaLaunchConfig_t cfg = {};
    cfg.gridDim = dim3(grid, 1, 1);
    cfg.blockDim = dim3(block, 1, 1);
    cfg.dynamicSmemBytes = 0;
    cfg.stream = 0;
    cudaLaunchAttribute attr[1];
    attr[0].id = cudaLaunchAttributeProgrammaticStreamSerialization;
    attr[0].val.programmaticStreamSerializationAllowed = 1;
    cfg.attrs = attr;
    cfg.numAttrs = 1;
    cudaLaunchKernelEx(&cfg, kern, args...);
}

extern "C" void kernel_launch(void* const* d_in, const int* in_sizes, int n_in,
                              void* d_out, int out_size) {
    const float* x     = (const float*)d_in[0];
    const int*   eidx  = (const int*)  d_in[1];
    const int*   batch = (const int*)  d_in[2];
    const float* lin_w = (const float*)d_in[3];
    const float* lin_b = (const float*)d_in[4];
    const float* gcn_w = (const float*)d_in[5];
    const float* gcn_b = (const float*)d_in[6];
    const float* r1_w  = (const float*)d_in[7];
    const float* r1_b  = (const float*)d_in[8];
    const float* r2_w  = (const float*)d_in[9];
    const float* r2_b  = (const float*)d_in[10];
    float* out = (float*)d_out;

    const int* src = eidx;          // edge_index[0]
    const int* dst = eidx + NE;     // edge_index[1]

    int nb = (NN + 255) / 256;                 // 196
    int cb = (NE + 8 * 256 - 1) / (8 * 256);   // 782
    int eb = (NE + 2 * 256 - 1) / (2 * 256);   // 3125

    launch_pdl(k_count, cb, 256, dst);
    launch_pdl(k_prep,  nb, 256, x);

    launch_pdl(k_edge,  eb, 256, src, dst);    // acc1 = A u0
    launch_pdl(k_node<1>, nb, 256);            // z1, u1
    launch_pdl(k_edge,  eb, 256, src, dst);    // acc2 = A u1
    launch_pdl(k_node<2>, nb, 256);            // z2, u2
    launch_pdl(k_edge,  eb, 256, src, dst);    // acc3 = A u2
    launch_pdl(k_node3_pool, nb, 256, batch);  // z3 + pool -> g_S

    launch_pdl(k_readout, 1, 512,
               lin_w, lin_b, gcn_w, gcn_b, r1_w, r1_b, r2_w, r2_b, out);
}

// round 13
// speedup vs baseline: 1.0569x; 1.0569x over previous
#include <cuda_runtime.h>

// ---------------------------------------------------------------------------
// PureGNN rank collapse, u-scaled form, multi-launch + PDL:
//   u_k = dinv .* z_k ; edge: acc[d] += u_k[s] ; node: z=dinv*(acc+u), u=dinv*z
// Basis after 3 layers: [P^3 x, P^3 1, P^2 1, P 1, 1]; pooled S -> tiny readout.
// Self-restoring invariants (no init kernel): g_deg==0 restored by k_prep,
// g_S==0 restored by k_readout; loader zero-init provides the first epoch.
// RULES: __device__ globals only referenced in device code (ATS trap).
//        PDL pre-sync code reads ONLY pure inputs or K-2-or-older data.
//        Atomic-bound kernels: FEWER edges/thread = faster (R10/R12 lesson).
// ---------------------------------------------------------------------------

#define NN 50000
#define NE 1600000
#define NG 32
#define ED 128

__device__ float  g_deg [NN];     // invariant: 0 at kernel_launch entry
__device__ float  g_dinv[NN];
__device__ float2 g_u   [NN];     // current u_k
__device__ float2 g_acc [NN];     // edge accumulator
__device__ float  g_k1y [NN];     // z1.y
__device__ float  g_k2y [NN];     // z2.y
__device__ float  g_S   [NG * 5]; // invariant: 0 at kernel_launch entry

// ---------------------------------------------------------------------------
// degree count: 4 edges/thread (1563 blocks), indices pre-loaded; deg starts 0.
__global__ void k_count(const int* __restrict__ dst) {
    int e = (blockIdx.x * blockDim.x + threadIdx.x) * 4;
    int4 d4;
    bool full = (e + 3 < NE);
    if (full) d4 = *(const int4*)(dst + e);         // pure input: safe pre-sync
    cudaGridDependencySynchronize();                // prior replay's readout done
    if (full) {
        atomicAdd(&g_deg[d4.x], 1.0f);
        atomicAdd(&g_deg[d4.y], 1.0f);
        atomicAdd(&g_deg[d4.z], 1.0f);
        atomicAdd(&g_deg[d4.w], 1.0f);
    } else {
        for (; e < NE; e++) atomicAdd(&g_deg[dst[e]], 1.0f);
    }
    cudaTriggerProgrammaticLaunchCompletion();
}

// dinv = rsqrt(deg+1)  (+1 = self-loop); restore deg=0; u0; acc=0
__global__ void k_prep(const float* __restrict__ x) {
    int i = blockIdx.x * blockDim.x + threadIdx.x;
    float xi = 0.0f;
    if (i < NN) xi = x[i];
    cudaGridDependencySynchronize();                // wait for k_count
    if (i >= NN) return;
    float di = rsqrtf(g_deg[i] + 1.0f);
    g_deg[i] = 0.0f;                                // restore invariant
    g_dinv[i] = di;
    g_u[i]   = make_float2(di * xi, di);
    g_acc[i] = make_float2(0.0f, 0.0f);
}

// edge pass: acc[d] += u[s], ONE edge/thread (6250 blocks, max concurrency)
__global__ void k_edge(const int* __restrict__ src, const int* __restrict__ dst) {
    int e = blockIdx.x * blockDim.x + threadIdx.x;
    int s = 0, d = 0;
    bool ok = (e < NE);
    if (ok) { s = src[e]; d = dst[e]; }             // pure input: safe pre-sync
    cudaGridDependencySynchronize();                // wait for u from prior kernel
    if (ok) atomicAdd(&g_acc[d], __ldg(&g_u[s]));
    cudaTriggerProgrammaticLaunchCompletion();
}

// node pass K (1 or 2): z = dinv*(acc+u); stash z.y; u = dinv*z; acc = 0
// dinv/u are K-2-or-older -> safe pre-sync; acc needs the sync.
template <int K>
__global__ void k_node() {
    int i = blockIdx.x * blockDim.x + threadIdx.x;
    float di = 0.0f; float2 u = make_float2(0.0f, 0.0f);
    if (i < NN) { di = g_dinv[i]; u = g_u[i]; }
    cudaGridDependencySynchronize();                // wait for acc from edge pass
    if (i >= NN) return;
    float2 a = g_acc[i];
    float zx = di * (a.x + u.x);
    float zy = di * (a.y + u.y);
    if (K == 1) g_k1y[i] = zy;
    else        g_k2y[i] = zy;
    g_u[i]   = make_float2(di * zx, di * zy);
    g_acc[i] = make_float2(0.0f, 0.0f);
}

// node3 + per-graph pooling (batch sorted -> warp-uniform fast path).
__global__ void k_node3_pool(const int* __restrict__ batch) {
    __shared__ float sh[NG * 5];
    int i = blockIdx.x * blockDim.x + threadIdx.x;
    int lane = threadIdx.x & 31;
    bool act = (i < NN);
    int g = 0;
    if (act) g = batch[i];                          // pure input: safe pre-sync
    for (int t = threadIdx.x; t < NG * 5; t += blockDim.x) sh[t] = 0.0f;
    __syncthreads();

    cudaGridDependencySynchronize();                // wait for acc3

    float z3x = 0.0f, z3y = 0.0f, k2 = 0.0f, k1 = 0.0f;
    if (act) {
        float di = g_dinv[i];
        float2 a = g_acc[i];
        float2 u = g_u[i];
        z3x = di * (a.x + u.x);
        z3y = di * (a.y + u.y);
        k2  = g_k2y[i];
        k1  = g_k1y[i];
    }
    unsigned m = __ballot_sync(0xffffffffu, act);
    int g0 = __shfl_sync(0xffffffffu, g, 0);
    bool uni = (m == 0xffffffffu) && __all_sync(0xffffffffu, g == g0);
    if (uni) {
        #pragma unroll
        for (int o = 16; o > 0; o >>= 1) {
            z3x += __shfl_down_sync(0xffffffffu, z3x, o);
            z3y += __shfl_down_sync(0xffffffffu, z3y, o);
            k2  += __shfl_down_sync(0xffffffffu, k2,  o);
            k1  += __shfl_down_sync(0xffffffffu, k1,  o);
        }
        if (lane == 0) {
            atomicAdd(&sh[g0 * 5 + 0], z3x);
            atomicAdd(&sh[g0 * 5 + 1], z3y);
            atomicAdd(&sh[g0 * 5 + 2], k2);
            atomicAdd(&sh[g0 * 5 + 3], k1);
            atomicAdd(&sh[g0 * 5 + 4], 32.0f);
        }
    } else if (act) {
        atomicAdd(&sh[g * 5 + 0], z3x);
        atomicAdd(&sh[g * 5 + 1], z3y);
        atomicAdd(&sh[g * 5 + 2], k2);
        atomicAdd(&sh[g * 5 + 3], k1);
        atomicAdd(&sh[g * 5 + 4], 1.0f);
    }
    __syncthreads();
    for (int t = threadIdx.x; t < NG * 5; t += blockDim.x)
        if (sh[t] != 0.0f) atomicAdd(&g_S[t], sh[t]);
    cudaTriggerProgrammaticLaunchCompletion();
}

// ---------------------------------------------------------------------------
// Readout (PDL): weight chain pre-sync (overlaps the pool); g_S read post-sync
// and zeroed to restore the replay invariant.
// ---------------------------------------------------------------------------
__global__ void k_readout(const float* __restrict__ lin_w, const float* __restrict__ lin_b,
                          const float* __restrict__ gcn_w, const float* __restrict__ gcn_b,
                          const float* __restrict__ r1_w,  const float* __restrict__ r1_b,
                          const float* __restrict__ r2_w,  const float* __restrict__ r2_b,
                          float* __restrict__ out) {
    __shared__ float vin[5][ED];
    __shared__ float vout[5][ED];
    __shared__ float pooled[NG][ED];
    __shared__ float hr[NG][ED];
    __shared__ float sS[NG * 5];

    int tid = threadIdx.x;
    int j   = tid & 127;
    int grp = tid >> 7;      // 0..3

    if (grp == 0) { vin[0][j] = lin_w[j]; vin[1][j] = lin_b[j]; }  // pure inputs
    __syncthreads();

    int nrows = 2;
    for (int l = 0; l < 3; l++) {
        const float* W = gcn_w + l * ED * ED;
        if (grp < nrows) {
            float a0 = 0.0f, a1 = 0.0f;
            #pragma unroll 4
            for (int i = 0; i < ED; i += 2) {
                a0 = fmaf(vin[grp][i],     W[i * ED + j],       a0);
                a1 = fmaf(vin[grp][i + 1], W[(i + 1) * ED + j], a1);
            }
            vout[grp][j] = a0 + a1;
        }
        if (grp == 0) vout[nrows][j] = gcn_b[l * ED + j];
        nrows++;
        __syncthreads();
        for (int r = grp; r < nrows; r += 4) vin[r][j] = vout[r][j];
        __syncthreads();
    }

    cudaGridDependencySynchronize();          // g_S ready
    for (int t = tid; t < NG * 5; t += 512) { sS[t] = g_S[t]; g_S[t] = 0.0f; }
    __syncthreads();

    for (int g = grp * 8; g < grp * 8 + 8; g++) {
        float p = 0.0f;
        #pragma unroll
        for (int r = 0; r < 5; r++) p = fmaf(sS[g * 5 + r], vin[r][j], p);
        pooled[g][j] = p;
    }
    __syncthreads();

    float bj = r1_b[j];
    for (int g = grp * 8; g < grp * 8 + 8; g++) {
        float a0 = bj, a1 = 0.0f, a2 = 0.0f, a3 = 0.0f;
        #pragma unroll 2
        for (int i = 0; i < ED; i += 4) {
            a0 = fmaf(pooled[g][i],     r1_w[i * ED + j],       a0);
            a1 = fmaf(pooled[g][i + 1], r1_w[(i + 1) * ED + j], a1);
            a2 = fmaf(pooled[g][i + 2], r1_w[(i + 2) * ED + j], a2);
            a3 = fmaf(pooled[g][i + 3], r1_w[(i + 3) * ED + j], a3);
        }
        hr[g][j] = tanhf((a0 + a1) + (a2 + a3));
    }
    __syncthreads();

    int warp = tid >> 5;
    int lane = tid & 31;
    for (int g = warp; g < NG; g += 16) {
        float s = hr[g][lane]      * r2_w[lane]
                + hr[g][lane + 32] * r2_w[lane + 32]
                + hr[g][lane + 64] * r2_w[lane + 64]
                + hr[g][lane + 96] * r2_w[lane + 96];
        #pragma unroll
        for (int o = 16; o > 0; o >>= 1) s += __shfl_down_sync(0xffffffffu, s, o);
        if (lane == 0) out[g] = s + r2_b[0];
    }
}

// ---------------------------------------------------------------------------
template <typename KernT, typename... Args>
static inline void launch_pdl(KernT kern, int grid, int block, Args... args) {
    cudaLaunchConfig_t cfg = {};
    cfg.gridDim = dim3(grid, 1, 1);
    cfg.blockDim = dim3(block, 1, 1);
    cfg.dynamicSmemBytes = 0;
    cfg.stream = 0;
    cudaLaunchAttribute attr[1];
    attr[0].id = cudaLaunchAttributeProgrammaticStreamSerialization;
    attr[0].val.programmaticStreamSerializationAllowed = 1;
    cfg.attrs = attr;
    cfg.numAttrs = 1;
    cudaLaunchKernelEx(&cfg, kern, args...);
}

extern "C" void kernel_launch(void* const* d_in, const int* in_sizes, int n_in,
                              void* d_out, int out_size) {
    const float* x     = (const float*)d_in[0];
    const int*   eidx  = (const int*)  d_in[1];
    const int*   batch = (const int*)  d_in[2];
    const float* lin_w = (const float*)d_in[3];
    const float* lin_b = (const float*)d_in[4];
    const float* gcn_w = (const float*)d_in[5];
    const float* gcn_b = (const float*)d_in[6];
    const float* r1_w  = (const float*)d_in[7];
    const float* r1_b  = (const float*)d_in[8];
    const float* r2_w  = (const float*)d_in[9];
    const float* r2_b  = (const float*)d_in[10];
    float* out = (float*)d_out;

    const int* src = eidx;          // edge_index[0]
    const int* dst = eidx + NE;     // edge_index[1]

    int nb = (NN + 255) / 256;                 // 196
    int cb = (NE + 4 * 256 - 1) / (4 * 256);   // 1563
    int eb = (NE + 255) / 256;                 // 6250

    launch_pdl(k_count, cb, 256, dst);
    launch_pdl(k_prep,  nb, 256, x);

    launch_pdl(k_edge,  eb, 256, src, dst);    // acc1 = A u0
    launch_pdl(k_node<1>, nb, 256);            // z1, u1
    launch_pdl(k_edge,  eb, 256, src, dst);    // acc2 = A u1
    launch_pdl(k_node<2>, nb, 256);            // z2, u2
    launch_pdl(k_edge,  eb, 256, src, dst);    // acc3 = A u2
    launch_pdl(k_node3_pool, nb, 256, batch);  // z3 + pool -> g_S

    launch_pdl(k_readout, 1, 512,
               lin_w, lin_b, gcn_w, gcn_b, r1_w, r1_b, r2_w, r2_b, out);
}

// round 14
// speedup vs baseline: 1.0624x; 1.0052x over previous
#include <cuda_runtime.h>

// ---------------------------------------------------------------------------
// PureGNN rank collapse, u-scaled form, multi-launch + PDL:
//   u_k = dinv .* z_k ; edge: acc[d] += u_k[s] ; node: z=dinv*(acc+u), u=dinv*z
// Basis after 3 layers: [P^3 x, P^3 1, P^2 1, P 1, 1]; pooled S -> tiny readout.
// Self-restoring invariants (no init kernel): g_deg==0 restored by k_prep,
// g_S==0 restored by k_readout; loader zero-init provides the first epoch.
// RULES: __device__ globals only referenced in device code (ATS trap).
//        PDL pre-sync code reads ONLY pure inputs or K-2-or-older data.
//        Atomic-bound kernels: FEWER edges/thread = faster (R10/R12/R13).
// ---------------------------------------------------------------------------

#define NN 50000
#define NE 1600000
#define NG 32
#define ED 128

__device__ float  g_deg [NN];     // invariant: 0 at kernel_launch entry
__device__ float  g_dinv[NN];
__device__ float2 g_u   [NN];     // current u_k
__device__ float2 g_acc [NN];     // edge accumulator
__device__ float  g_k1y [NN];     // z1.y
__device__ float  g_k2y [NN];     // z2.y
__device__ float  g_S   [NG * 5]; // invariant: 0 at kernel_launch entry

// ---------------------------------------------------------------------------
// degree count: 2 edges/thread (3125 blocks), indices pre-loaded; deg starts 0.
__global__ void k_count(const int* __restrict__ dst) {
    int e = (blockIdx.x * blockDim.x + threadIdx.x) * 2;
    int2 d2;
    bool full = (e + 1 < NE);
    if (full) d2 = *(const int2*)(dst + e);         // pure input: safe pre-sync
    cudaGridDependencySynchronize();                // prior replay's readout done
    if (full) {
        atomicAdd(&g_deg[d2.x], 1.0f);
        atomicAdd(&g_deg[d2.y], 1.0f);
    } else if (e < NE) {
        atomicAdd(&g_deg[dst[e]], 1.0f);
    }
    cudaTriggerProgrammaticLaunchCompletion();
}

// dinv = rsqrt(deg+1)  (+1 = self-loop); restore deg=0; u0; acc=0
__global__ void k_prep(const float* __restrict__ x) {
    int i = blockIdx.x * blockDim.x + threadIdx.x;
    float xi = 0.0f;
    if (i < NN) xi = x[i];
    cudaGridDependencySynchronize();                // wait for k_count
    if (i >= NN) return;
    float di = rsqrtf(g_deg[i] + 1.0f);
    g_deg[i] = 0.0f;                                // restore invariant
    g_dinv[i] = di;
    g_u[i]   = make_float2(di * xi, di);
    g_acc[i] = make_float2(0.0f, 0.0f);
}

// edge pass: acc[d] += u[s], ONE edge/thread (6250 blocks, max concurrency)
__global__ void k_edge(const int* __restrict__ src, const int* __restrict__ dst) {
    int e = blockIdx.x * blockDim.x + threadIdx.x;
    int s = 0, d = 0;
    bool ok = (e < NE);
    if (ok) { s = src[e]; d = dst[e]; }             // pure input: safe pre-sync
    cudaGridDependencySynchronize();                // wait for u from prior kernel
    if (ok) atomicAdd(&g_acc[d], __ldg(&g_u[s]));
    cudaTriggerProgrammaticLaunchCompletion();
}

// node pass K (1 or 2): z = dinv*(acc+u); stash z.y; u = dinv*z; acc = 0
// dinv/u are K-2-or-older -> safe pre-sync; acc needs the sync.
template <int K>
__global__ void k_node() {
    int i = blockIdx.x * blockDim.x + threadIdx.x;
    float di = 0.0f; float2 u = make_float2(0.0f, 0.0f);
    if (i < NN) { di = g_dinv[i]; u = g_u[i]; }
    cudaGridDependencySynchronize();                // wait for acc from edge pass
    if (i >= NN) return;
    float2 a = g_acc[i];
    float zx = di * (a.x + u.x);
    float zy = di * (a.y + u.y);
    if (K == 1) g_k1y[i] = zy;
    else        g_k2y[i] = zy;
    g_u[i]   = make_float2(di * zx, di * zy);
    g_acc[i] = make_float2(0.0f, 0.0f);
}

// node3 + per-graph pooling (batch sorted -> warp-uniform fast path).
__global__ void k_node3_pool(const int* __restrict__ batch) {
    __shared__ float sh[NG * 5];
    int i = blockIdx.x * blockDim.x + threadIdx.x;
    int lane = threadIdx.x & 31;
    bool act = (i < NN);
    int g = 0;
    if (act) g = batch[i];                          // pure input: safe pre-sync
    for (int t = threadIdx.x; t < NG * 5; t += blockDim.x) sh[t] = 0.0f;
    __syncthreads();

    cudaGridDependencySynchronize();                // wait for acc3

    float z3x = 0.0f, z3y = 0.0f, k2 = 0.0f, k1 = 0.0f;
    if (act) {
        float di = g_dinv[i];
        float2 a = g_acc[i];
        float2 u = g_u[i];
        z3x = di * (a.x + u.x);
        z3y = di * (a.y + u.y);
        k2  = g_k2y[i];
        k1  = g_k1y[i];
    }
    unsigned m = __ballot_sync(0xffffffffu, act);
    int g0 = __shfl_sync(0xffffffffu, g, 0);
    bool uni = (m == 0xffffffffu) && __all_sync(0xffffffffu, g == g0);
    if (uni) {
        #pragma unroll
        for (int o = 16; o > 0; o >>= 1) {
            z3x += __shfl_down_sync(0xffffffffu, z3x, o);
            z3y += __shfl_down_sync(0xffffffffu, z3y, o);
            k2  += __shfl_down_sync(0xffffffffu, k2,  o);
            k1  += __shfl_down_sync(0xffffffffu, k1,  o);
        }
        if (lane == 0) {
            atomicAdd(&sh[g0 * 5 + 0], z3x);
            atomicAdd(&sh[g0 * 5 + 1], z3y);
            atomicAdd(&sh[g0 * 5 + 2], k2);
            atomicAdd(&sh[g0 * 5 + 3], k1);
            atomicAdd(&sh[g0 * 5 + 4], 32.0f);
        }
    } else if (act) {
        atomicAdd(&sh[g * 5 + 0], z3x);
        atomicAdd(&sh[g * 5 + 1], z3y);
        atomicAdd(&sh[g * 5 + 2], k2);
        atomicAdd(&sh[g * 5 + 3], k1);
        atomicAdd(&sh[g * 5 + 4], 1.0f);
    }
    __syncthreads();
    for (int t = threadIdx.x; t < NG * 5; t += blockDim.x)
        if (sh[t] != 0.0f) atomicAdd(&g_S[t], sh[t]);
    cudaTriggerProgrammaticLaunchCompletion();
}

// ---------------------------------------------------------------------------
// Readout (PDL): weight chain pre-sync (overlaps the pool); g_S read post-sync
// and zeroed to restore the replay invariant.
// ---------------------------------------------------------------------------
__global__ void k_readout(const float* __restrict__ lin_w, const float* __restrict__ lin_b,
                          const float* __restrict__ gcn_w, const float* __restrict__ gcn_b,
                          const float* __restrict__ r1_w,  const float* __restrict__ r1_b,
                          const float* __restrict__ r2_w,  const float* __restrict__ r2_b,
                          float* __restrict__ out) {
    __shared__ float vin[5][ED];
    __shared__ float vout[5][ED];
    __shared__ float pooled[NG][ED];
    __shared__ float hr[NG][ED];
    __shared__ float sS[NG * 5];

    int tid = threadIdx.x;
    int j   = tid & 127;
    int grp = tid >> 7;      // 0..3

    if (grp == 0) { vin[0][j] = lin_w[j]; vin[1][j] = lin_b[j]; }  // pure inputs
    __syncthreads();

    int nrows = 2;
    for (int l = 0; l < 3; l++) {
        const float* W = gcn_w + l * ED * ED;
        if (grp < nrows) {
            float a0 = 0.0f, a1 = 0.0f;
            #pragma unroll 4
            for (int i = 0; i < ED; i += 2) {
                a0 = fmaf(vin[grp][i],     W[i * ED + j],       a0);
                a1 = fmaf(vin[grp][i + 1], W[(i + 1) * ED + j], a1);
            }
            vout[grp][j] = a0 + a1;
        }
        if (grp == 0) vout[nrows][j] = gcn_b[l * ED + j];
        nrows++;
        __syncthreads();
        for (int r = grp; r < nrows; r += 4) vin[r][j] = vout[r][j];
        __syncthreads();
    }

    cudaGridDependencySynchronize();          // g_S ready
    for (int t = tid; t < NG * 5; t += 512) { sS[t] = g_S[t]; g_S[t] = 0.0f; }
    __syncthreads();

    for (int g = grp * 8; g < grp * 8 + 8; g++) {
        float p = 0.0f;
        #pragma unroll
        for (int r = 0; r < 5; r++) p = fmaf(sS[g * 5 + r], vin[r][j], p);
        pooled[g][j] = p;
    }
    __syncthreads();

    float bj = r1_b[j];
    for (int g = grp * 8; g < grp * 8 + 8; g++) {
        float a0 = bj, a1 = 0.0f, a2 = 0.0f, a3 = 0.0f;
        #pragma unroll 2
        for (int i = 0; i < ED; i += 4) {
            a0 = fmaf(pooled[g][i],     r1_w[i * ED + j],       a0);
            a1 = fmaf(pooled[g][i + 1], r1_w[(i + 1) * ED + j], a1);
            a2 = fmaf(pooled[g][i + 2], r1_w[(i + 2) * ED + j], a2);
            a3 = fmaf(pooled[g][i + 3], r1_w[(i + 3) * ED + j], a3);
        }
        hr[g][j] = tanhf((a0 + a1) + (a2 + a3));
    }
    __syncthreads();

    int warp = tid >> 5;
    int lane = tid & 31;
    for (int g = warp; g < NG; g += 16) {
        float s = hr[g][lane]      * r2_w[lane]
                + hr[g][lane + 32] * r2_w[lane + 32]
                + hr[g][lane + 64] * r2_w[lane + 64]
                + hr[g][lane + 96] * r2_w[lane + 96];
        #pragma unroll
        for (int o = 16; o > 0; o >>= 1) s += __shfl_down_sync(0xffffffffu, s, o);
        if (lane == 0) out[g] = s + r2_b[0];
    }
}

// ---------------------------------------------------------------------------
template <typename KernT, typename... Args>
static inline void launch_pdl(KernT kern, int grid, int block, Args... args) {
    cudaLaunchConfig_t cfg = {};
    cfg.gridDim = dim3(grid, 1, 1);
    cfg.blockDim = dim3(block, 1, 1);
    cfg.dynamicSmemBytes = 0;
    cfg.stream = 0;
    cudaLaunchAttribute attr[1];
    attr[0].id = cudaLaunchAttributeProgrammaticStreamSerialization;
    attr[0].val.programmaticStreamSerializationAllowed = 1;
    cfg.attrs = attr;
    cfg.numAttrs = 1;
    cudaLaunchKernelEx(&cfg, kern, args...);
}

extern "C" void kernel_launch(void* const* d_in, const int* in_sizes, int n_in,
                              void* d_out, int out_size) {
    const float* x     = (const float*)d_in[0];
    const int*   eidx  = (const int*)  d_in[1];
    const int*   batch = (const int*)  d_in[2];
    const float* lin_w = (const float*)d_in[3];
    const float* lin_b = (const float*)d_in[4];
    const float* gcn_w = (const float*)d_in[5];
    const float* gcn_b = (const float*)d_in[6];
    const float* r1_w  = (const float*)d_in[7];
    const float* r1_b  = (const float*)d_in[8];
    const float* r2_w  = (const float*)d_in[9];
    const float* r2_b  = (const float*)d_in[10];
    float* out = (float*)d_out;

    const int* src = eidx;          // edge_index[0]
    const int* dst = eidx + NE;     // edge_index[1]

    int nb = (NN + 255) / 256;                 // 196
    int cb = (NE + 2 * 256 - 1) / (2 * 256);   // 3125
    int eb = (NE + 255) / 256;                 // 6250

    launch_pdl(k_count, cb, 256, dst);
    launch_pdl(k_prep,  nb, 256, x);

    launch_pdl(k_edge,  eb, 256, src, dst);    // acc1 = A u0
    launch_pdl(k_node<1>, nb, 256);            // z1, u1
    launch_pdl(k_edge,  eb, 256, src, dst);    // acc2 = A u1
    launch_pdl(k_node<2>, nb, 256);            // z2, u2
    launch_pdl(k_edge,  eb, 256, src, dst);    // acc3 = A u2
    launch_pdl(k_node3_pool, nb, 256, batch);  // z3 + pool -> g_S

    launch_pdl(k_readout, 1, 512,
               lin_w, lin_b, gcn_w, gcn_b, r1_w, r1_b, r2_w, r2_b, out);
}